// round 7
// baseline (speedup 1.0000x reference)
#include <cuda_runtime.h>
#include <math.h>

#define Bb 128
#define Tt 100
#define Dd 2048
#define Hh 1024
#define Oo 20
#define BH (Bb*Hh)          // 131072
#define TW 91               // T - WINDOW + 1

typedef unsigned long long ull;

// packed fp32x2 FMA: d = a*b + d, per-lane IEEE fma.rn (bit-identical to fmaf)
__device__ __forceinline__ void ffma2(ull& d, ull a, ull b) {
    asm("fma.rn.f32x2 %0, %1, %2, %0;" : "+l"(d) : "l"(a), "l"(b));
}
__device__ __forceinline__ ull bcast2(float x) {
    ull r; unsigned xi = __float_as_uint(x);
    asm("mov.b64 %0, {%1, %2};" : "=l"(r) : "r"(xi), "r"(xi));
    return r;
}
union f4u2 { float4 f; ull u[2]; };

// ---------------- device scratch ----------
__device__ float g_A[Tt*BH];         // input projection G1, layout [(b*Tt+t)][h]
__device__ float g_S[Tt*BH];         // spike history [t][b*H+h]
__device__ float g_hmem[BH];
__device__ float g_omem[Bb*Oo];
__device__ float g_osum[Bb*Oo];
__device__ float g_nbr[Tt];

// ---------------- init -------------------------------------------------------
__global__ void k_init(const float* __restrict__ hm, const float* __restrict__ om) {
    int idx = blockIdx.x * blockDim.x + threadIdx.x;
    if (idx < BH)                        g_hmem[idx] = hm[idx];
    else if (idx < BH + Bb*Oo)           g_omem[idx - BH] = om[idx - BH];
    else if (idx < BH + 2*Bb*Oo)         g_osum[idx - BH - Bb*Oo] = 0.f;
    else if (idx < BH + 2*Bb*Oo + Tt)    g_nbr[idx - BH - 2*Bb*Oo] = 0.f;
}

// ---------------- input GEMM: g_A = X @ Wi2h^T  (f32x2, 8x8/thread) ---------
// Sequential ascending-k, single accumulator per output element (bit-exact).
// C[12800,1024], K=2048. BM=128, BN=128, BK=16, 256 threads.
__global__ __launch_bounds__(256) void k_ingemm(
    const float* __restrict__ X, const float* __restrict__ W)
{
    __shared__ float As[2][16][132];
    __shared__ float Bs[2][16][132];
    const int m0 = blockIdx.y * 128;
    const int n0 = blockIdx.x * 128;
    const int tid = threadIdx.x;
    const int lr = tid >> 2;            // 0..63
    const int lc = (tid & 3) << 2;      // 0,4,8,12
    const int tm = tid & 15, tn = tid >> 4;

    ull c2[8][4];
#pragma unroll
    for (int i = 0; i < 8; i++)
#pragma unroll
        for (int p = 0; p < 4; p++) c2[i][p] = 0ULL;

    const float* pa0 = X + (size_t)(m0 + lr) * Dd + lc;
    const float* pa1 = X + (size_t)(m0 + lr + 64) * Dd + lc;
    const float* pb0 = W + (size_t)(n0 + lr) * Dd + lc;
    const float* pb1 = W + (size_t)(n0 + lr + 64) * Dd + lc;

    float4 ra0 = *(const float4*)(pa0);
    float4 ra1 = *(const float4*)(pa1);
    float4 rb0 = *(const float4*)(pb0);
    float4 rb1 = *(const float4*)(pb1);
#pragma unroll
    for (int j = 0; j < 4; j++) {
        As[0][lc + j][lr]      = ((const float*)&ra0)[j];
        As[0][lc + j][lr + 64] = ((const float*)&ra1)[j];
        Bs[0][lc + j][lr]      = ((const float*)&rb0)[j];
        Bs[0][lc + j][lr + 64] = ((const float*)&rb1)[j];
    }
    __syncthreads();

    const int NK = Dd / 16;
    int buf = 0;
    for (int kt = 0; kt < NK; ++kt) {
        if (kt + 1 < NK) {
            int ko = (kt + 1) * 16;
            ra0 = *(const float4*)(pa0 + ko);
            ra1 = *(const float4*)(pa1 + ko);
            rb0 = *(const float4*)(pb0 + ko);
            rb1 = *(const float4*)(pb1 + ko);
        }
#pragma unroll
        for (int kk = 0; kk < 16; ++kk) {
            float4 a0 = *(const float4*)&As[buf][kk][tm * 4];
            float4 a1 = *(const float4*)&As[buf][kk][tm * 4 + 64];
            f4u2 b0, b1;
            b0.f = *(const float4*)&Bs[buf][kk][tn * 4];
            b1.f = *(const float4*)&Bs[buf][kk][tn * 4 + 64];
            ull bp[4] = {b0.u[0], b0.u[1], b1.u[0], b1.u[1]};
            float av[8] = {a0.x,a0.y,a0.z,a0.w,a1.x,a1.y,a1.z,a1.w};
#pragma unroll
            for (int i = 0; i < 8; i++) {
                ull ap = bcast2(av[i]);
#pragma unroll
                for (int p = 0; p < 4; p++) ffma2(c2[i][p], ap, bp[p]);
            }
        }
        if (kt + 1 < NK) {
            int nb = buf ^ 1;
#pragma unroll
            for (int j = 0; j < 4; j++) {
                As[nb][lc + j][lr]      = ((const float*)&ra0)[j];
                As[nb][lc + j][lr + 64] = ((const float*)&ra1)[j];
                Bs[nb][lc + j][lr]      = ((const float*)&rb0)[j];
                Bs[nb][lc + j][lr + 64] = ((const float*)&rb1)[j];
            }
        }
        buf ^= 1;
        __syncthreads();
    }

#pragma unroll
    for (int i = 0; i < 8; i++) {
        int row = m0 + tm * 4 + (i & 3) + ((i >= 4) ? 64 : 0);
#pragma unroll
        for (int jg = 0; jg < 2; jg++) {
            f4u2 v;
            v.u[0] = c2[i][2 * jg];
            v.u[1] = c2[i][2 * jg + 1];
            *(float4*)&g_A[(size_t)row * Hh + n0 + tn * 4 + jg * 64] = v.f;
        }
    }
}

// ---------------- fused step kernel ----------------------------------------
// grid 136 blocks x 256 threads:
//   blocks 0..127 : recur 32x32 tile for step t (R3 code) + hidden membrane
//   blocks 128..135: output layer for step t-1, 16 batches each (2 at a time)
__global__ __launch_bounds__(256) void k_step(
    const float* __restrict__ hs0, const float* __restrict__ W,
    const float* __restrict__ b1, const float* __restrict__ b2,
    const float* __restrict__ thr_h,
    const float* __restrict__ W2, const float* __restrict__ b2o,
    const float* __restrict__ thr_o, int t)
{
    const int tid = threadIdx.x;
    const int bid = blockIdx.x;

    if (bid < 128) {
        // ---------- recurrent GEMM tile + hidden membrane ----------
        __shared__ float As[2][32][34];
        __shared__ float Bs[2][32][34];
        __shared__ float red[256];

        const int m0 = (bid >> 5) * 32;      // batch tile
        const int n0 = (bid & 31) * 32;      // hidden tile
        const int lr = tid >> 3;
        const int lc = (tid & 7) << 2;
        const int txm = tid & 15, txn = tid >> 4;

        const float* Amat = (t == 0) ? hs0 : (g_S + (size_t)(t - 1) * BH);
        const float* pa = Amat + (size_t)(m0 + lr) * Hh + lc;
        const float* pb = W + (size_t)(n0 + lr) * Hh + lc;

        float a00 = 0.f, a01 = 0.f, a10 = 0.f, a11 = 0.f;

        float4 ra = *(const float4*)pa;
        float4 rb = *(const float4*)pb;
#pragma unroll
        for (int j = 0; j < 4; j++) {
            As[0][lc + j][lr] = ((const float*)&ra)[j];
            Bs[0][lc + j][lr] = ((const float*)&rb)[j];
        }
        __syncthreads();

        const int NK = Hh / 32;   // 32
        int buf = 0;
        for (int kt = 0; kt < NK; ++kt) {
            if (kt + 1 < NK) {
                ra = *(const float4*)(pa + (kt + 1) * 32);
                rb = *(const float4*)(pb + (kt + 1) * 32);
            }
#pragma unroll
            for (int kk = 0; kk < 32; ++kk) {
                float2 a = *(const float2*)&As[buf][kk][txm * 2];
                float2 b = *(const float2*)&Bs[buf][kk][txn * 2];
                a00 = fmaf(a.x, b.x, a00);
                a01 = fmaf(a.x, b.y, a01);
                a10 = fmaf(a.y, b.x, a10);
                a11 = fmaf(a.y, b.y, a11);
            }
            if (kt + 1 < NK) {
                int nb = buf ^ 1;
#pragma unroll
                for (int j = 0; j < 4; j++) {
                    As[nb][lc + j][lr] = ((const float*)&ra)[j];
                    Bs[nb][lc + j][lr] = ((const float*)&rb)[j];
                }
            }
            buf ^= 1;
            __syncthreads();
        }

        // fused hidden membrane update for this block's 4 elements
        const int m = m0 + txm * 2, n = n0 + txn * 2;
        float accs[4] = {a00, a01, a10, a11};
        float spsum = 0.f;
#pragma unroll
        for (int e = 0; e < 4; e++) {
            int mm = m + (e >> 1);
            int nn = n + (e & 1);
            int bh = mm * Hh + nn;
            float G1 = g_A[((size_t)mm * Tt + t) * Hh + nn];
            float v = ((G1 + b1[nn]) + accs[e]) + b2[nn];
            float mem = g_hmem[bh] + v;
            float th = thr_h[nn];
            float sp = (mem - th > 0.f) ? 1.f : 0.f;
            mem = mem * (1.f - sp);
            float neg = (mem < -th) ? 1.f : 0.f;
            mem = mem * (1.f - neg) - th * neg;
            g_hmem[bh] = mem;
            g_S[(size_t)t * BH + bh] = sp;
            spsum += sp;
        }
        red[tid] = spsum;
        __syncthreads();
        for (int s = 128; s > 0; s >>= 1) {
            if (tid < s) red[tid] += red[tid + s];
            __syncthreads();
        }
        if (tid == 0) atomicAdd(&g_nbr[t], red[0] * (1.f / Bb));
    } else {
        // ---------- output layer for step t-1 (2 batches at a time) ----------
        if (t == 0) return;
        __shared__ float rs2[2][Oo][128];
        __shared__ float spsm2[2][Oo];
        const int g = tid >> 7;          // 0 or 1
        const int ltid = tid & 127;
        const int tprev = t - 1;
        for (int it = 0; it < 8; ++it) {
            int b = (bid - 128) * 16 + it * 2 + g;
            const float* hs = g_S + (size_t)tprev * BH + (size_t)b * Hh;
            float acc[Oo];
#pragma unroll
            for (int o = 0; o < Oo; o++) acc[o] = 0.f;
            for (int k = ltid; k < Hh; k += 128) {
                float h = hs[k];
#pragma unroll
                for (int o = 0; o < Oo; o++) acc[o] = fmaf(h, W2[o * Hh + k], acc[o]);
            }
#pragma unroll
            for (int o = 0; o < Oo; o++) rs2[g][o][ltid] = acc[o];
            __syncthreads();
            for (int s = 64; s > 0; s >>= 1) {
                if (ltid < s)
#pragma unroll
                    for (int o = 0; o < Oo; o++) rs2[g][o][ltid] += rs2[g][o][ltid + s];
                __syncthreads();
            }
            if (ltid < Oo) {
                int o = ltid;
                float m = g_omem[b * Oo + o] + (rs2[g][o][0] + b2o[o]);
                float th = thr_o[o];
                float sp = (m - th > 0.f) ? 1.f : 0.f;
                m = m * (1.f - sp);
                float neg = (m < -th) ? 1.f : 0.f;
                m = m * (1.f - neg) - th * neg;
                g_omem[b * Oo + o] = m;
                g_osum[b * Oo + o] += sp;
                spsm2[g][o] = sp;
            }
            __syncthreads();
            if (ltid == 0) {
                float s = 0.f;
                for (int o = 0; o < Oo; o++) s += spsm2[g][o];
                atomicAdd(&g_nbr[tprev], s * (1.f / Bb));
            }
            __syncthreads();
        }
    }
}

// ---------------- final output-layer step (t = Tt-1) ------------------------
__global__ __launch_bounds__(128) void k_out99(const float* __restrict__ W2,
    const float* __restrict__ b2o, const float* __restrict__ thr_o)
{
    __shared__ float rs[Oo][128];
    __shared__ float spsm[Oo];
    const int t = Tt - 1;
    int b = blockIdx.x, tid = threadIdx.x;
    const float* hs = g_S + (size_t)t * BH + (size_t)b * Hh;
    float acc[Oo];
#pragma unroll
    for (int o = 0; o < Oo; o++) acc[o] = 0.f;
    for (int k = tid; k < Hh; k += 128) {
        float h = hs[k];
#pragma unroll
        for (int o = 0; o < Oo; o++) acc[o] = fmaf(h, W2[o * Hh + k], acc[o]);
    }
#pragma unroll
    for (int o = 0; o < Oo; o++) rs[o][tid] = acc[o];
    __syncthreads();
    for (int s = 64; s > 0; s >>= 1) {
        if (tid < s)
#pragma unroll
            for (int o = 0; o < Oo; o++) rs[o][tid] += rs[o][tid + s];
        __syncthreads();
    }
    if (tid < Oo) {
        int o = tid;
        float m = g_omem[b * Oo + o] + (rs[o][0] + b2o[o]);
        float th = thr_o[o];
        float sp = (m - th > 0.f) ? 1.f : 0.f;
        m = m * (1.f - sp);
        float neg = (m < -th) ? 1.f : 0.f;
        m = m * (1.f - neg) - th * neg;
        g_omem[b * Oo + o] = m;
        g_osum[b * Oo + o] += sp;
        spsm[o] = sp;
    }
    __syncthreads();
    if (tid == 0) {
        float s = 0.f;
        for (int o = 0; o < Oo; o++) s += spsm[o];
        atomicAdd(&g_nbr[t], s * (1.f / Bb));
    }
}

// ---------------- sliding-window filter ------------------------------------
__global__ __launch_bounds__(128) void k_filt(float* __restrict__ out) {
    __shared__ float sm[128 * TW];
    int bh = blockIdx.x * 128 + threadIdx.x;
    const float* S = g_S + bh;
    float s = 0.f;
#pragma unroll
    for (int tt = 0; tt < 10; ++tt) s += S[(size_t)tt * BH];
    sm[threadIdx.x * TW + 0] = s / 10.0f;
    for (int tt = 10; tt < Tt; ++tt) {
        s += S[(size_t)tt * BH] - S[(size_t)(tt - 10) * BH];
        sm[threadIdx.x * TW + (tt - 9)] = s / 10.0f;
    }
    __syncthreads();
    float* dst = out + 229 + (size_t)blockIdx.x * 128 * TW;
    for (int idx = threadIdx.x; idx < 128 * TW; idx += 128) dst[idx] = sm[idx];
}

// ---------------- predictions / loss / nbr_events --------------------------
__global__ void k_final(const int* __restrict__ labels, float* __restrict__ out) {
    int tid = threadIdx.x;  // 256 threads
    __shared__ float red[128];
    if (tid < 128) {
        int b = tid;
        float mx = g_osum[b * Oo];
        int arg = 0;
        for (int o = 1; o < Oo; o++) {
            float v = g_osum[b * Oo + o];
            if (v > mx) { mx = v; arg = o; }
        }
        float se = 0.f;
        for (int o = 0; o < Oo; o++) se += expf(g_osum[b * Oo + o] - mx);
        float lse = mx + logf(se);
        out[b] = (float)arg;
        int lab = labels[b];
        red[b] = -(g_osum[b * Oo + lab] - lse);
    }
    __syncthreads();
    for (int s = 64; s > 0; s >>= 1) {
        if (tid < s) red[tid] += red[tid + s];
        __syncthreads();
    }
    if (tid == 0) out[128] = red[0] / (float)Bb;
    if (tid >= 128 && tid < 128 + Tt) out[129 + (tid - 128)] = g_nbr[tid - 128];
}

// ---------------- launcher --------------------------------------------------
extern "C" void kernel_launch(void* const* d_in, const int* in_sizes, int n_in,
                              void* d_out, int out_size) {
    const float* input = (const float*)d_in[0];
    const int*   labels = (const int*)d_in[1];
    const float* hmem0 = (const float*)d_in[2];
    const float* hspk0 = (const float*)d_in[3];
    const float* omem0 = (const float*)d_in[4];
    const float* Wi2h  = (const float*)d_in[6];
    const float* bi2h  = (const float*)d_in[7];
    const float* Wh2h  = (const float*)d_in[8];
    const float* bh2h  = (const float*)d_in[9];
    const float* Wh2o  = (const float*)d_in[10];
    const float* bh2o  = (const float*)d_in[11];
    const float* thr_h = (const float*)d_in[12];
    const float* thr_o = (const float*)d_in[13];
    float* out = (float*)d_out;

    int initN = BH + 2 * Bb * Oo + Tt;
    k_init<<<(initN + 255) / 256, 256>>>(hmem0, omem0);
    k_ingemm<<<dim3(Hh / 128, (Bb * Tt) / 128), 256>>>(input, Wi2h);
    for (int t = 0; t < Tt; ++t) {
        k_step<<<136, 256>>>(hspk0, Wh2h, bi2h, bh2h, thr_h,
                             Wh2o, bh2o, thr_o, t);
    }
    k_out99<<<Bb, 128>>>(Wh2o, bh2o, thr_o);
    k_filt<<<BH / 128, 128>>>(out);
    k_final<<<1, 256>>>(labels, out);
}

// round 8
// speedup vs baseline: 4.1817x; 4.1817x over previous
#include <cuda_runtime.h>
#include <math.h>

#define Bb 128
#define Tt 100
#define Dd 2048
#define Hh 1024
#define Oo 20
#define BH (Bb*Hh)          // 131072
#define TW 91               // T - WINDOW + 1

typedef unsigned long long ull;

// packed fp32x2 FMA: d = a*b + d, per-lane IEEE fma.rn (bit-identical to fmaf)
__device__ __forceinline__ void ffma2(ull& d, ull a, ull b) {
    asm("fma.rn.f32x2 %0, %1, %2, %0;" : "+l"(d) : "l"(a), "l"(b));
}
__device__ __forceinline__ ull bcast2(float x) {
    ull r; unsigned xi = __float_as_uint(x);
    asm("mov.b64 %0, {%1, %2};" : "=l"(r) : "r"(xi), "r"(xi));
    return r;
}
union f4u2 { float4 f; ull u[2]; };

// ---------------- device scratch ----------
__device__ float g_A[Tt*BH];         // input projection G1, layout [(b*Tt+t)][h]
__device__ float g_S[Tt*BH];         // spike history [t][b*H+h]
__device__ float g_WT[Hh*Hh];        // Wh2h transposed: WT[k][n]
__device__ float g_hmem[BH];
__device__ float g_omem[Bb*Oo];
__device__ float g_osum[Bb*Oo];
__device__ float g_nbr[Tt];

// ---------------- init -------------------------------------------------------
__global__ void k_init(const float* __restrict__ hm, const float* __restrict__ om) {
    int idx = blockIdx.x * blockDim.x + threadIdx.x;
    if (idx < BH)                        g_hmem[idx] = hm[idx];
    else if (idx < BH + Bb*Oo)           g_omem[idx - BH] = om[idx - BH];
    else if (idx < BH + 2*Bb*Oo)         g_osum[idx - BH - Bb*Oo] = 0.f;
    else if (idx < BH + 2*Bb*Oo + Tt)    g_nbr[idx - BH - 2*Bb*Oo] = 0.f;
}

// ---------------- transpose Wh2h -> WT[k][n] --------------------------------
__global__ __launch_bounds__(256) void k_transp(const float* __restrict__ W) {
    __shared__ float tile[32][33];
    int bx = blockIdx.x % 32, by = blockIdx.x / 32;   // 32x32 tile grid
    int lx = threadIdx.x & 31, ly = threadIdx.x >> 5; // 32x8
#pragma unroll
    for (int r = 0; r < 4; r++) {
        int n = by * 32 + ly + r * 8;
        tile[ly + r * 8][lx] = W[(size_t)n * Hh + bx * 32 + lx];
    }
    __syncthreads();
#pragma unroll
    for (int r = 0; r < 4; r++) {
        int k = bx * 32 + ly + r * 8;
        g_WT[(size_t)k * Hh + by * 32 + lx] = tile[lx][ly + r * 8];
    }
}

// ---------------- input GEMM: g_A = X @ Wi2h^T  (f32x2, 8x8/thread) ---------
// Sequential ascending-k, single accumulator per output element (bit-exact).
__global__ __launch_bounds__(256) void k_ingemm(
    const float* __restrict__ X, const float* __restrict__ W)
{
    __shared__ float As[2][16][132];
    __shared__ float Bs[2][16][132];
    const int m0 = blockIdx.y * 128;
    const int n0 = blockIdx.x * 128;
    const int tid = threadIdx.x;
    const int lr = tid >> 2;
    const int lc = (tid & 3) << 2;
    const int tm = tid & 15, tn = tid >> 4;

    ull c2[8][4];
#pragma unroll
    for (int i = 0; i < 8; i++)
#pragma unroll
        for (int p = 0; p < 4; p++) c2[i][p] = 0ULL;

    const float* pa0 = X + (size_t)(m0 + lr) * Dd + lc;
    const float* pa1 = X + (size_t)(m0 + lr + 64) * Dd + lc;
    const float* pb0 = W + (size_t)(n0 + lr) * Dd + lc;
    const float* pb1 = W + (size_t)(n0 + lr + 64) * Dd + lc;

    float4 ra0 = *(const float4*)(pa0);
    float4 ra1 = *(const float4*)(pa1);
    float4 rb0 = *(const float4*)(pb0);
    float4 rb1 = *(const float4*)(pb1);
#pragma unroll
    for (int j = 0; j < 4; j++) {
        As[0][lc + j][lr]      = ((const float*)&ra0)[j];
        As[0][lc + j][lr + 64] = ((const float*)&ra1)[j];
        Bs[0][lc + j][lr]      = ((const float*)&rb0)[j];
        Bs[0][lc + j][lr + 64] = ((const float*)&rb1)[j];
    }
    __syncthreads();

    const int NK = Dd / 16;
    int buf = 0;
    for (int kt = 0; kt < NK; ++kt) {
        if (kt + 1 < NK) {
            int ko = (kt + 1) * 16;
            ra0 = *(const float4*)(pa0 + ko);
            ra1 = *(const float4*)(pa1 + ko);
            rb0 = *(const float4*)(pb0 + ko);
            rb1 = *(const float4*)(pb1 + ko);
        }
#pragma unroll
        for (int kk = 0; kk < 16; ++kk) {
            float4 a0 = *(const float4*)&As[buf][kk][tm * 4];
            float4 a1 = *(const float4*)&As[buf][kk][tm * 4 + 64];
            f4u2 b0, b1;
            b0.f = *(const float4*)&Bs[buf][kk][tn * 4];
            b1.f = *(const float4*)&Bs[buf][kk][tn * 4 + 64];
            ull bp[4] = {b0.u[0], b0.u[1], b1.u[0], b1.u[1]};
            float av[8] = {a0.x,a0.y,a0.z,a0.w,a1.x,a1.y,a1.z,a1.w};
#pragma unroll
            for (int i = 0; i < 8; i++) {
                ull ap = bcast2(av[i]);
#pragma unroll
                for (int p = 0; p < 4; p++) ffma2(c2[i][p], ap, bp[p]);
            }
        }
        if (kt + 1 < NK) {
            int nb = buf ^ 1;
#pragma unroll
            for (int j = 0; j < 4; j++) {
                As[nb][lc + j][lr]      = ((const float*)&ra0)[j];
                As[nb][lc + j][lr + 64] = ((const float*)&ra1)[j];
                Bs[nb][lc + j][lr]      = ((const float*)&rb0)[j];
                Bs[nb][lc + j][lr + 64] = ((const float*)&rb1)[j];
            }
        }
        buf ^= 1;
        __syncthreads();
    }

#pragma unroll
    for (int i = 0; i < 8; i++) {
        int row = m0 + tm * 4 + (i & 3) + ((i >= 4) ? 64 : 0);
#pragma unroll
        for (int jg = 0; jg < 2; jg++) {
            f4u2 v;
            v.u[0] = c2[i][2 * jg];
            v.u[1] = c2[i][2 * jg + 1];
            *(float4*)&g_A[(size_t)row * Hh + n0 + tn * 4 + jg * 64] = v.f;
        }
    }
}

// ---------------- fused step kernel ----------------------------------------
// grid 256 x 256 threads:
//   blocks 0..127  : sparse recurrent accumulate for batch b=bid at step t
//                    + hidden membrane update (bit-exact vs dense fmaf chain)
//   blocks 128..255: output layer for step t-1, batch b=bid-128 (R3 code)
__global__ __launch_bounds__(256) void k_step(
    const float* __restrict__ hs0,
    const float* __restrict__ b1, const float* __restrict__ b2,
    const float* __restrict__ thr_h,
    const float* __restrict__ W2, const float* __restrict__ b2o,
    const float* __restrict__ thr_o, int t)
{
    const int tid = threadIdx.x;
    const int bid = blockIdx.x;

    if (bid < 128) {
        // ---------- sparse recur + hidden membrane for batch b ----------
        __shared__ float sflag[Hh];
        __shared__ int   list[Hh];
        __shared__ int   scnt;
        __shared__ float red[256];
        const int b = bid;

        const float* hs = (t == 0) ? (hs0 + (size_t)b * Hh)
                                   : (g_S + (size_t)(t - 1) * BH + (size_t)b * Hh);
        // load spike flags
        *(float4*)&sflag[tid * 4] = *(const float4*)&hs[tid * 4];
        __syncthreads();

        // warp 0: ordered stream compaction of active k (ascending)
        if (tid < 32) {
            int base = 0;
            for (int c = 0; c < 32; ++c) {
                float v = sflag[c * 32 + tid];
                unsigned m = __ballot_sync(0xffffffffu, v != 0.f);
                if (v != 0.f) {
                    int pre = __popc(m & ((1u << tid) - 1u));
                    list[base + pre] = c * 32 + tid;
                }
                base += __popc(m);
            }
            if (tid == 0) scnt = base;
        }
        __syncthreads();
        const int cnt = scnt;

        // accumulate acc[n] = sum_{active k, ascending} WT[k][n]
        // thread owns n = 4*tid .. 4*tid+3  (== fmaf chain bits: +w for 1, skip for 0)
        float a0 = 0.f, a1 = 0.f, a2 = 0.f, a3 = 0.f;
        int j = 0;
        for (; j + 4 <= cnt; j += 4) {
            int k0 = list[j], k1 = list[j + 1], k2 = list[j + 2], k3 = list[j + 3];
            float4 w0 = *(const float4*)&g_WT[(size_t)k0 * Hh + tid * 4];
            float4 w1 = *(const float4*)&g_WT[(size_t)k1 * Hh + tid * 4];
            float4 w2 = *(const float4*)&g_WT[(size_t)k2 * Hh + tid * 4];
            float4 w3 = *(const float4*)&g_WT[(size_t)k3 * Hh + tid * 4];
            a0 += w0.x; a1 += w0.y; a2 += w0.z; a3 += w0.w;
            a0 += w1.x; a1 += w1.y; a2 += w1.z; a3 += w1.w;
            a0 += w2.x; a1 += w2.y; a2 += w2.z; a3 += w2.w;
            a0 += w3.x; a1 += w3.y; a2 += w3.z; a3 += w3.w;
        }
        for (; j < cnt; ++j) {
            int k = list[j];
            float4 w = *(const float4*)&g_WT[(size_t)k * Hh + tid * 4];
            a0 += w.x; a1 += w.y; a2 += w.z; a3 += w.w;
        }

        // hidden membrane update for n = 4*tid..4*tid+3
        float accs[4] = {a0, a1, a2, a3};
        float4 G1 = *(const float4*)&g_A[((size_t)b * Tt + t) * Hh + tid * 4];
        float4 bb1 = *(const float4*)&b1[tid * 4];
        float4 bb2 = *(const float4*)&b2[tid * 4];
        float4 th4 = *(const float4*)&thr_h[tid * 4];
        float g1v[4] = {G1.x, G1.y, G1.z, G1.w};
        float b1v[4] = {bb1.x, bb1.y, bb1.z, bb1.w};
        float b2v[4] = {bb2.x, bb2.y, bb2.z, bb2.w};
        float thv[4] = {th4.x, th4.y, th4.z, th4.w};
        float spv[4];
        float spsum = 0.f;
#pragma unroll
        for (int e = 0; e < 4; e++) {
            int bh = b * Hh + tid * 4 + e;
            float v = ((g1v[e] + b1v[e]) + accs[e]) + b2v[e];
            float mem = g_hmem[bh] + v;
            float th = thv[e];
            float sp = (mem - th > 0.f) ? 1.f : 0.f;
            mem = mem * (1.f - sp);
            float neg = (mem < -th) ? 1.f : 0.f;
            mem = mem * (1.f - neg) - th * neg;
            g_hmem[bh] = mem;
            spv[e] = sp;
            spsum += sp;
        }
        *(float4*)&g_S[(size_t)t * BH + b * Hh + tid * 4]
            = make_float4(spv[0], spv[1], spv[2], spv[3]);

        red[tid] = spsum;
        __syncthreads();
        for (int s = 128; s > 0; s >>= 1) {
            if (tid < s) red[tid] += red[tid + s];
            __syncthreads();
        }
        if (tid == 0) atomicAdd(&g_nbr[t], red[0] * (1.f / Bb));
    } else {
        // ---------- output layer for step t-1, one batch per block ----------
        if (t == 0) return;
        __shared__ float rs[Oo][128];
        __shared__ float spsm[Oo];
        const int b = bid - 128;
        const int tprev = t - 1;
        const float* hs = g_S + (size_t)tprev * BH + (size_t)b * Hh;
        if (tid < 128) {
            float acc[Oo];
#pragma unroll
            for (int o = 0; o < Oo; o++) acc[o] = 0.f;
            for (int k = tid; k < Hh; k += 128) {
                float h = hs[k];
#pragma unroll
                for (int o = 0; o < Oo; o++) acc[o] = fmaf(h, W2[o * Hh + k], acc[o]);
            }
#pragma unroll
            for (int o = 0; o < Oo; o++) rs[o][tid] = acc[o];
        }
        __syncthreads();
        for (int s = 64; s > 0; s >>= 1) {
            if (tid < s)
#pragma unroll
                for (int o = 0; o < Oo; o++) rs[o][tid] += rs[o][tid + s];
            __syncthreads();
        }
        if (tid < Oo) {
            int o = tid;
            float m = g_omem[b * Oo + o] + (rs[o][0] + b2o[o]);
            float th = thr_o[o];
            float sp = (m - th > 0.f) ? 1.f : 0.f;
            m = m * (1.f - sp);
            float neg = (m < -th) ? 1.f : 0.f;
            m = m * (1.f - neg) - th * neg;
            g_omem[b * Oo + o] = m;
            g_osum[b * Oo + o] += sp;
            spsm[o] = sp;
        }
        __syncthreads();
        if (tid == 0) {
            float s = 0.f;
            for (int o = 0; o < Oo; o++) s += spsm[o];
            atomicAdd(&g_nbr[tprev], s * (1.f / Bb));
        }
    }
}

// ---------------- final output-layer step (t = Tt-1) ------------------------
__global__ __launch_bounds__(128) void k_out99(const float* __restrict__ W2,
    const float* __restrict__ b2o, const float* __restrict__ thr_o)
{
    __shared__ float rs[Oo][128];
    __shared__ float spsm[Oo];
    const int t = Tt - 1;
    int b = blockIdx.x, tid = threadIdx.x;
    const float* hs = g_S + (size_t)t * BH + (size_t)b * Hh;
    float acc[Oo];
#pragma unroll
    for (int o = 0; o < Oo; o++) acc[o] = 0.f;
    for (int k = tid; k < Hh; k += 128) {
        float h = hs[k];
#pragma unroll
        for (int o = 0; o < Oo; o++) acc[o] = fmaf(h, W2[o * Hh + k], acc[o]);
    }
#pragma unroll
    for (int o = 0; o < Oo; o++) rs[o][tid] = acc[o];
    __syncthreads();
    for (int s = 64; s > 0; s >>= 1) {
        if (tid < s)
#pragma unroll
            for (int o = 0; o < Oo; o++) rs[o][tid] += rs[o][tid + s];
        __syncthreads();
    }
    if (tid < Oo) {
        int o = tid;
        float m = g_omem[b * Oo + o] + (rs[o][0] + b2o[o]);
        float th = thr_o[o];
        float sp = (m - th > 0.f) ? 1.f : 0.f;
        m = m * (1.f - sp);
        float neg = (m < -th) ? 1.f : 0.f;
        m = m * (1.f - neg) - th * neg;
        g_omem[b * Oo + o] = m;
        g_osum[b * Oo + o] += sp;
        spsm[o] = sp;
    }
    __syncthreads();
    if (tid == 0) {
        float s = 0.f;
        for (int o = 0; o < Oo; o++) s += spsm[o];
        atomicAdd(&g_nbr[t], s * (1.f / Bb));
    }
}

// ---------------- sliding-window filter ------------------------------------
__global__ __launch_bounds__(128) void k_filt(float* __restrict__ out) {
    __shared__ float sm[128 * TW];
    int bh = blockIdx.x * 128 + threadIdx.x;
    const float* S = g_S + bh;
    float s = 0.f;
#pragma unroll
    for (int tt = 0; tt < 10; ++tt) s += S[(size_t)tt * BH];
    sm[threadIdx.x * TW + 0] = s / 10.0f;
    for (int tt = 10; tt < Tt; ++tt) {
        s += S[(size_t)tt * BH] - S[(size_t)(tt - 10) * BH];
        sm[threadIdx.x * TW + (tt - 9)] = s / 10.0f;
    }
    __syncthreads();
    float* dst = out + 229 + (size_t)blockIdx.x * 128 * TW;
    for (int idx = threadIdx.x; idx < 128 * TW; idx += 128) dst[idx] = sm[idx];
}

// ---------------- predictions / loss / nbr_events --------------------------
__global__ void k_final(const int* __restrict__ labels, float* __restrict__ out) {
    int tid = threadIdx.x;  // 256 threads
    __shared__ float red[128];
    if (tid < 128) {
        int b = tid;
        float mx = g_osum[b * Oo];
        int arg = 0;
        for (int o = 1; o < Oo; o++) {
            float v = g_osum[b * Oo + o];
            if (v > mx) { mx = v; arg = o; }
        }
        float se = 0.f;
        for (int o = 0; o < Oo; o++) se += expf(g_osum[b * Oo + o] - mx);
        float lse = mx + logf(se);
        out[b] = (float)arg;
        int lab = labels[b];
        red[b] = -(g_osum[b * Oo + lab] - lse);
    }
    __syncthreads();
    for (int s = 64; s > 0; s >>= 1) {
        if (tid < s) red[tid] += red[tid + s];
        __syncthreads();
    }
    if (tid == 0) out[128] = red[0] / (float)Bb;
    if (tid >= 128 && tid < 128 + Tt) out[129 + (tid - 128)] = g_nbr[tid - 128];
}

// ---------------- launcher --------------------------------------------------
extern "C" void kernel_launch(void* const* d_in, const int* in_sizes, int n_in,
                              void* d_out, int out_size) {
    const float* input = (const float*)d_in[0];
    const int*   labels = (const int*)d_in[1];
    const float* hmem0 = (const float*)d_in[2];
    const float* hspk0 = (const float*)d_in[3];
    const float* omem0 = (const float*)d_in[4];
    const float* Wi2h  = (const float*)d_in[6];
    const float* bi2h  = (const float*)d_in[7];
    const float* Wh2h  = (const float*)d_in[8];
    const float* bh2h  = (const float*)d_in[9];
    const float* Wh2o  = (const float*)d_in[10];
    const float* bh2o  = (const float*)d_in[11];
    const float* thr_h = (const float*)d_in[12];
    const float* thr_o = (const float*)d_in[13];
    float* out = (float*)d_out;

    int initN = BH + 2 * Bb * Oo + Tt;
    k_init<<<(initN + 255) / 256, 256>>>(hmem0, omem0);
    k_transp<<<1024, 256>>>(Wh2h);
    k_ingemm<<<dim3(Hh / 128, (Bb * Tt) / 128), 256>>>(input, Wi2h);
    for (int t = 0; t < Tt; ++t) {
        k_step<<<256, 256>>>(hspk0, bi2h, bh2h, thr_h,
                             Wh2o, bh2o, thr_o, t);
    }
    k_out99<<<Bb, 128>>>(Wh2o, bh2o, thr_o);
    k_filt<<<BH / 128, 128>>>(out);
    k_final<<<1, 256>>>(labels, out);
}